// round 3
// baseline (speedup 1.0000x reference)
#include <cuda_runtime.h>
#include <cuda_bf16.h>
#include <cstdint>

#define N_NODES 100000
#define N_EDGES 1600000
#define D 64

// ---------------- scratch (static device globals; no allocation) ----------------
__device__ __align__(16) float  g_t[(size_t)N_NODES * D];   // transformed features
__device__ __align__(16) float  g_agg[(size_t)N_NODES * D]; // scatter-add accumulator
__device__ __align__(16) float  g_deginv[N_NODES];          // 1/max(out_degree,1)
__device__ __align__(16) double g_msum[D];                  // mean accumulator
__device__ int g_is64;                                      // index dtype flag

// ---------------- index dtype detection ------------------------------------------
// JAX silently downcasts int64->int32 without x64 mode; detect which we got.
// If the buffer is int32, reading 256 int64s touches only 2KB (safe), and the
// packed pairs are astronomically unlikely to all decode into [0, N_NODES).
__global__ void gcn_detect_idx(const void* __restrict__ src) {
    const long long* p = (const long long*)src;
    int ok = 1;
    for (int i = 0; i < 256; i++) {
        long long v = p[i];
        if (v < 0 || v >= N_NODES) { ok = 0; break; }
    }
    g_is64 = ok;
}

__device__ __forceinline__ int idx_at(const void* __restrict__ p, int e, int is64) {
    return is64 ? (int)((const long long*)p)[e] : ((const int*)p)[e];
}

// ---------------- init: zero agg, deg accumulator, mean accumulator -------------
__global__ void gcn_init() {
    size_t i = (size_t)blockIdx.x * blockDim.x + threadIdx.x;
    if (i < (size_t)N_NODES * D) g_agg[i] = 0.0f;
    if (i < N_NODES)             g_deginv[i] = 0.0f;
    if (i < D)                   g_msum[i] = 0.0;
}

__global__ void gcn_zero_agg() {
    size_t i = (size_t)blockIdx.x * blockDim.x + threadIdx.x;
    if (i < (size_t)N_NODES * D) g_agg[i] = 0.0f;
}

// ---------------- out-degree -----------------------------------------------------
__global__ void gcn_deg(const void* __restrict__ src) {
    int e = blockIdx.x * blockDim.x + threadIdx.x;
    if (e >= N_EDGES) return;
    int s = idx_at(src, e, g_is64);
    if ((unsigned)s < N_NODES) atomicAdd(&g_deginv[s], 1.0f);
}

__global__ void gcn_deg_inv() {
    int i = blockIdx.x * blockDim.x + threadIdx.x;
    if (i < N_NODES) g_deginv[i] = 1.0f / fmaxf(g_deginv[i], 1.0f);
}

// ---------------- fused prologue + GEMM ------------------------------------------
// g_t[n,:] = prologue(in[n,:]) @ W
// prologue(x) = (use_relu ? relu(x + bias) : x) * deg_inv[n]
// Input: in_ext if non-null (layer 0 = harness features), else g_agg.
__global__ __launch_bounds__(256) void gcn_gemm(
    const float* __restrict__ in_ext, const float* __restrict__ W,
    const float* __restrict__ bias, int use_relu)
{
    __shared__ float Ws[D][D];      // 16 KB
    __shared__ float Xs[32][D + 1]; // padded against LDS conflicts

    const float* in = in_ext ? in_ext : g_agg;

    const int tid = threadIdx.x;
    const int n0  = blockIdx.x * 32;

    {
        const float4* w4 = (const float4*)W;
        float4* ws4 = (float4*)&Ws[0][0];
        #pragma unroll
        for (int i = tid; i < (D * D) / 4; i += 256) ws4[i] = w4[i];
    }
    for (int i = tid; i < 32 * D; i += 256) {
        int r = i >> 6, k = i & 63;
        float x = in[(size_t)(n0 + r) * D + k];
        if (use_relu) x = fmaxf(x + bias[k], 0.0f);
        x *= g_deginv[n0 + r];
        Xs[r][k] = x;
    }
    __syncthreads();

    const int r  = tid >> 3;
    const int c0 = (tid & 7) * 8;
    float acc[8] = {0,0,0,0,0,0,0,0};

    #pragma unroll
    for (int k = 0; k < D; k++) {
        float x = Xs[r][k];
        float4 wA = *(const float4*)&Ws[k][c0];
        float4 wB = *(const float4*)&Ws[k][c0 + 4];
        acc[0] += x * wA.x; acc[1] += x * wA.y;
        acc[2] += x * wA.z; acc[3] += x * wA.w;
        acc[4] += x * wB.x; acc[5] += x * wB.y;
        acc[6] += x * wB.z; acc[7] += x * wB.w;
    }

    float* o = g_t + (size_t)(n0 + r) * D + c0;
    *(float4*)(o)     = make_float4(acc[0], acc[1], acc[2], acc[3]);
    *(float4*)(o + 4) = make_float4(acc[4], acc[5], acc[6], acc[7]);
}

// ---------------- edge scatter: g_agg[dst] += g_t[src] ----------------------------
// 16 threads per edge, each moves one float4 with a vector reduction.
__global__ __launch_bounds__(256) void gcn_scatter(
    const void* __restrict__ src, const void* __restrict__ dst)
{
    long long tid = (long long)blockIdx.x * blockDim.x + threadIdx.x;
    int e    = (int)(tid >> 4);
    int lane = (int)(tid & 15);
    if (e >= N_EDGES) return;

    const int is64 = g_is64;
    int s = idx_at(src, e, is64);
    int d = idx_at(dst, e, is64);
    if ((unsigned)s >= N_NODES || (unsigned)d >= N_NODES) return;

    const float4 v = __ldg((const float4*)(g_t + (size_t)s * D) + lane);
    float* pd = g_agg + (size_t)d * D + lane * 4;
    asm volatile("red.global.add.v4.f32 [%0], {%1,%2,%3,%4};"
                 :: "l"(pd), "f"(v.x), "f"(v.y), "f"(v.z), "f"(v.w)
                 : "memory");
}

// ---------------- finalize: h = agg + b2, accumulate column sums ------------------
__global__ __launch_bounds__(256) void gcn_finalize(
    const float* __restrict__ b2, float* __restrict__ out)
{
    const int j  = threadIdx.x & 63;   // global stride multiple of 64 -> column fixed
    const float bj = b2[j];
    float sum = 0.0f;

    const size_t total  = (size_t)N_NODES * D;
    const size_t stride = (size_t)gridDim.x * blockDim.x;
    for (size_t idx = (size_t)blockIdx.x * blockDim.x + threadIdx.x;
         idx < total; idx += stride) {
        float v = g_agg[idx] + bj;
        out[idx] = v;
        sum += v;
    }

    __shared__ float sdata[256];
    sdata[threadIdx.x] = sum;
    __syncthreads();
    if (threadIdx.x < 64) {
        float tot = sdata[threadIdx.x] + sdata[threadIdx.x + 64]
                  + sdata[threadIdx.x + 128] + sdata[threadIdx.x + 192];
        atomicAdd(&g_msum[threadIdx.x], (double)tot);
    }
}

__global__ void gcn_mean_write(float* __restrict__ out) {
    int j = threadIdx.x;
    if (j < D) out[(size_t)N_NODES * D + j] = (float)(g_msum[j] / (double)N_NODES);
}

// ---------------- launch ----------------------------------------------------------
extern "C" void kernel_launch(void* const* d_in, const int* in_sizes, int n_in,
                              void* d_out, int out_size)
{
    const float* features = (const float*)d_in[0];
    const void*  src      = d_in[1];
    const void*  dst      = d_in[2];
    const float* W0 = (const float*)d_in[3];
    const float* b0 = (const float*)d_in[4];
    const float* W1 = (const float*)d_in[5];
    const float* b1 = (const float*)d_in[6];
    const float* W2 = (const float*)d_in[7];
    const float* b2 = (const float*)d_in[8];
    float* out = (float*)d_out;

    const int threads      = 256;
    const int blocks_nd    = (int)(((size_t)N_NODES * D + threads - 1) / threads);
    const int blocks_edges = (N_EDGES + threads - 1) / threads;
    const int blocks_nodes = (N_NODES + threads - 1) / threads;
    const int blocks_gemm  = N_NODES / 32;
    const int blocks_scat  = (int)(((long long)N_EDGES * 16 + threads - 1) / threads);

    // dtype detection + degrees + zero scratch
    gcn_detect_idx<<<1, 1>>>(src);
    gcn_init<<<blocks_nd, threads>>>();
    gcn_deg<<<blocks_edges, threads>>>(src);
    gcn_deg_inv<<<blocks_nodes, threads>>>();

    // layer 0: input = features, output = g_t, scatter into g_agg
    gcn_gemm<<<blocks_gemm, threads>>>(features, W0, nullptr, 0);
    gcn_scatter<<<blocks_scat, threads>>>(src, dst);

    // layer 1: input = g_agg (selected in-kernel), re-zero, scatter
    gcn_gemm<<<blocks_gemm, threads>>>(nullptr, W1, b0, 1);
    gcn_zero_agg<<<blocks_nd, threads>>>();
    gcn_scatter<<<blocks_scat, threads>>>(src, dst);

    // layer 2
    gcn_gemm<<<blocks_gemm, threads>>>(nullptr, W2, b1, 1);
    gcn_zero_agg<<<blocks_nd, threads>>>();
    gcn_scatter<<<blocks_scat, threads>>>(src, dst);

    // epilogue: h = agg + b2, column mean
    gcn_finalize<<<512, threads>>>(b2, out);
    gcn_mean_write<<<1, 64>>>(out);
}

// round 4
// speedup vs baseline: 1.0075x; 1.0075x over previous
#include <cuda_runtime.h>
#include <cuda_bf16.h>
#include <cstdint>

#define N_NODES 100000
#define N_EDGES 1600000
#define D 64
#define EPT 4   // edges per 16-lane group in scatter

// ---------------- scratch (static device globals; no allocation) ----------------
__device__ __align__(16) float  g_t[(size_t)N_NODES * D];   // transformed features
__device__ __align__(16) float  g_agg[(size_t)N_NODES * D]; // scatter-add accumulator
__device__ __align__(16) int2   g_edge[N_EDGES];            // packed (src,dst) int32
__device__ __align__(16) float  g_deginv[N_NODES];          // 1/max(out_degree,1)
__device__ __align__(16) double g_msum[D];                  // mean accumulator
__device__ int g_is64;                                      // index dtype flag

// ---------------- index dtype detection ------------------------------------------
__global__ void gcn_detect_idx(const void* __restrict__ src) {
    const long long* p = (const long long*)src;
    int ok = 1;
    for (int i = 0; i < 256; i++) {
        long long v = p[i];
        if (v < 0 || v >= N_NODES) { ok = 0; break; }
    }
    g_is64 = ok;
}

__device__ __forceinline__ int idx_at(const void* __restrict__ p, int e, int is64) {
    return is64 ? (int)((const long long*)p)[e] : ((const int*)p)[e];
}

// ---------------- init -------------------------------------------------------------
__global__ void gcn_init() {
    size_t i = (size_t)blockIdx.x * blockDim.x + threadIdx.x;
    if (i < (size_t)N_NODES * D) g_agg[i] = 0.0f;
    if (i < N_NODES)             g_deginv[i] = 0.0f;
    if (i < D)                   g_msum[i] = 0.0;
}

// ---------------- prepass: pack indices + out-degree --------------------------------
__global__ void gcn_prep(const void* __restrict__ src, const void* __restrict__ dst) {
    int e = blockIdx.x * blockDim.x + threadIdx.x;
    if (e >= N_EDGES) return;
    const int is64 = g_is64;
    int s = idx_at(src, e, is64);
    int d = idx_at(dst, e, is64);
    if ((unsigned)s >= N_NODES) s = 0;
    if ((unsigned)d >= N_NODES) d = 0;
    g_edge[e] = make_int2(s, d);
    atomicAdd(&g_deginv[s], 1.0f);
}

__global__ void gcn_deg_inv() {
    int i = blockIdx.x * blockDim.x + threadIdx.x;
    if (i < N_NODES) g_deginv[i] = 1.0f / fmaxf(g_deginv[i], 1.0f);
}

// ---------------- fused prologue + GEMM (+ fused zeroing of consumed g_agg) --------
__global__ __launch_bounds__(256) void gcn_gemm(
    const float* __restrict__ in_ext, const float* __restrict__ W,
    const float* __restrict__ bias, int use_relu)
{
    __shared__ float Ws[D][D];      // 16 KB
    __shared__ float Xs[64][D + 1]; // 64 rows, padded

    const bool from_agg = (in_ext == nullptr);
    const float* in = from_agg ? g_agg : in_ext;

    const int tid = threadIdx.x;
    const int n0  = blockIdx.x * 64;

    {
        const float4* w4 = (const float4*)W;
        float4* ws4 = (float4*)&Ws[0][0];
        #pragma unroll
        for (int i = tid; i < (D * D) / 4; i += 256) ws4[i] = w4[i];
    }
    #pragma unroll 4
    for (int i = tid; i < 64 * D; i += 256) {
        int r = i >> 6, k = i & 63;
        int row = n0 + r;
        float x = 0.0f;
        if (row < N_NODES) {
            size_t idx = (size_t)row * D + k;
            x = in[idx];
            if (from_agg) g_agg[idx] = 0.0f;  // fused zeroing of consumed rows
            if (use_relu) x = fmaxf(x + bias[k], 0.0f);
            x *= g_deginv[row];
        }
        Xs[r][k] = x;
    }
    __syncthreads();

    const int r  = tid >> 2;          // local row 0..63
    const int c0 = (tid & 3) * 16;    // 16 output cols per thread
    float acc[16];
    #pragma unroll
    for (int i = 0; i < 16; i++) acc[i] = 0.0f;

    #pragma unroll
    for (int k = 0; k < D; k++) {
        float x = Xs[r][k];
        #pragma unroll
        for (int q = 0; q < 4; q++) {
            float4 w = *(const float4*)&Ws[k][c0 + q * 4];
            acc[q*4+0] += x * w.x; acc[q*4+1] += x * w.y;
            acc[q*4+2] += x * w.z; acc[q*4+3] += x * w.w;
        }
    }

    int row = n0 + r;
    if (row < N_NODES) {
        float* o = g_t + (size_t)row * D + c0;
        #pragma unroll
        for (int q = 0; q < 4; q++)
            *(float4*)(o + q * 4) = make_float4(acc[q*4+0], acc[q*4+1],
                                                acc[q*4+2], acc[q*4+3]);
    }
}

// ---------------- edge scatter: 4 edges per 16-lane group ---------------------------
__global__ __launch_bounds__(256) void gcn_scatter()
{
    int gid  = (blockIdx.x * blockDim.x + threadIdx.x) >> 4;
    int lane = threadIdx.x & 15;
    int e0   = gid * EPT;
    if (e0 >= N_EDGES) return;

    int2 sd[EPT];
    #pragma unroll
    for (int i = 0; i < EPT; i++) sd[i] = g_edge[e0 + i];  // N_EDGES % EPT == 0

    float4 v[EPT];
    #pragma unroll
    for (int i = 0; i < EPT; i++)
        v[i] = __ldg((const float4*)(g_t + (size_t)sd[i].x * D) + lane);

    #pragma unroll
    for (int i = 0; i < EPT; i++) {
        float* pd = g_agg + (size_t)sd[i].y * D + lane * 4;
        asm volatile("red.global.add.v4.f32 [%0], {%1,%2,%3,%4};"
                     :: "l"(pd), "f"(v[i].x), "f"(v[i].y), "f"(v[i].z), "f"(v[i].w)
                     : "memory");
    }
}

// ---------------- finalize + mean ----------------------------------------------------
__global__ __launch_bounds__(256) void gcn_finalize(
    const float* __restrict__ b2, float* __restrict__ out)
{
    const int j  = threadIdx.x & 63;
    const float bj = b2[j];
    float sum = 0.0f;

    const size_t total  = (size_t)N_NODES * D;
    const size_t stride = (size_t)gridDim.x * blockDim.x;
    for (size_t idx = (size_t)blockIdx.x * blockDim.x + threadIdx.x;
         idx < total; idx += stride) {
        float v = g_agg[idx] + bj;
        out[idx] = v;
        sum += v;
    }

    __shared__ float sdata[256];
    sdata[threadIdx.x] = sum;
    __syncthreads();
    if (threadIdx.x < 64) {
        float tot = sdata[threadIdx.x] + sdata[threadIdx.x + 64]
                  + sdata[threadIdx.x + 128] + sdata[threadIdx.x + 192];
        atomicAdd(&g_msum[threadIdx.x], (double)tot);
    }
}

__global__ void gcn_mean_write(float* __restrict__ out) {
    int j = threadIdx.x;
    if (j < D) out[(size_t)N_NODES * D + j] = (float)(g_msum[j] / (double)N_NODES);
}

// ---------------- launch --------------------------------------------------------------
extern "C" void kernel_launch(void* const* d_in, const int* in_sizes, int n_in,
                              void* d_out, int out_size)
{
    const float* features = (const float*)d_in[0];
    const void*  src      = d_in[1];
    const void*  dst      = d_in[2];
    const float* W0 = (const float*)d_in[3];
    const float* b0 = (const float*)d_in[4];
    const float* W1 = (const float*)d_in[5];
    const float* b1 = (const float*)d_in[6];
    const float* W2 = (const float*)d_in[7];
    const float* b2 = (const float*)d_in[8];
    float* out = (float*)d_out;

    const int threads      = 256;
    const int blocks_nd    = (int)(((size_t)N_NODES * D + threads - 1) / threads);
    const int blocks_edges = (N_EDGES + threads - 1) / threads;
    const int blocks_nodes = (N_NODES + threads - 1) / threads;
    const int blocks_gemm  = (N_NODES + 63) / 64;
    const int blocks_scat  = (int)(((long long)(N_EDGES / EPT) * 16 + threads - 1) / threads);

    gcn_detect_idx<<<1, 1>>>(src);
    gcn_init<<<blocks_nd, threads>>>();
    gcn_prep<<<blocks_edges, threads>>>(src, dst);
    gcn_deg_inv<<<blocks_nodes, threads>>>();

    gcn_gemm<<<blocks_gemm, threads>>>(features, W0, nullptr, 0);
    gcn_scatter<<<blocks_scat, threads>>>();

    gcn_gemm<<<blocks_gemm, threads>>>(nullptr, W1, b0, 1);
    gcn_scatter<<<blocks_scat, threads>>>();

    gcn_gemm<<<blocks_gemm, threads>>>(nullptr, W2, b1, 1);
    gcn_scatter<<<blocks_scat, threads>>>();

    gcn_finalize<<<512, threads>>>(b2, out);
    gcn_mean_write<<<1, 64>>>(out);
}

// round 5
// speedup vs baseline: 1.4071x; 1.3967x over previous
#include <cuda_runtime.h>
#include <cuda_bf16.h>
#include <cstdint>

#define N_NODES 100000
#define N_EDGES 1600000
#define D 64
#define SCAN_BLOCKS 391   // ceil(N_NODES/256)

// ---------------- scratch (static device globals; no allocation) ----------------
__device__ __align__(16) float  g_t[(size_t)N_NODES * D];   // transformed features
__device__ __align__(16) float  g_agg[(size_t)N_NODES * D]; // aggregation output
__device__ __align__(16) int2   g_edge[N_EDGES];            // packed (src,dst)
__device__ __align__(16) int    g_csr[N_EDGES];             // src ids grouped by dst
__device__ __align__(16) int    g_rowptr[N_NODES + 1];
__device__ __align__(16) int    g_woff[N_NODES];            // fill cursors
__device__ __align__(16) int    g_cnt[N_NODES];             // in-degree (dst) histogram
__device__ __align__(16) float  g_deginv[N_NODES];          // 1/max(out_degree,1)
__device__ __align__(16) int    g_bsum[SCAN_BLOCKS];        // scan partials
__device__ __align__(16) int    g_bsum_ex[SCAN_BLOCKS];
__device__ __align__(16) double g_msum[D];
__device__ int g_is64;

// ---------------- index dtype detection (JAX int64 silently -> int32) -------------
__global__ void gcn_detect_idx(const void* __restrict__ src) {
    const long long* p = (const long long*)src;
    int ok = 1;
    for (int i = 0; i < 256; i++) {
        long long v = p[i];
        if (v < 0 || v >= N_NODES) { ok = 0; break; }
    }
    g_is64 = ok;
}

__device__ __forceinline__ int idx_at(const void* __restrict__ p, int e, int is64) {
    return is64 ? (int)((const long long*)p)[e] : ((const int*)p)[e];
}

// ---------------- init: zero histograms + mean accumulator -------------------------
__global__ void gcn_init() {
    int i = blockIdx.x * blockDim.x + threadIdx.x;
    if (i < N_NODES) { g_cnt[i] = 0; g_deginv[i] = 0.0f; }
    if (i < D)       g_msum[i] = 0.0;
}

// ---------------- prepass: pack edges + both histograms ----------------------------
__global__ void gcn_prep(const void* __restrict__ src, const void* __restrict__ dst) {
    int e = blockIdx.x * blockDim.x + threadIdx.x;
    if (e >= N_EDGES) return;
    const int is64 = g_is64;
    int s = idx_at(src, e, is64);
    int d = idx_at(dst, e, is64);
    if ((unsigned)s >= N_NODES) s = 0;
    if ((unsigned)d >= N_NODES) d = 0;
    g_edge[e] = make_int2(s, d);
    atomicAdd(&g_deginv[s], 1.0f);   // out-degree (as float, inverted later)
    atomicAdd(&g_cnt[d], 1);         // in-degree for CSR
}

// ---------------- scan stage 1: per-block sums --------------------------------------
__global__ __launch_bounds__(256) void gcn_scan1() {
    __shared__ int sh[256];
    int i = blockIdx.x * 256 + threadIdx.x;
    int c = (i < N_NODES) ? g_cnt[i] : 0;
    sh[threadIdx.x] = c;
    __syncthreads();
    for (int off = 128; off > 0; off >>= 1) {
        if (threadIdx.x < off) sh[threadIdx.x] += sh[threadIdx.x + off];
        __syncthreads();
    }
    if (threadIdx.x == 0) g_bsum[blockIdx.x] = sh[0];
}

// ---------------- scan stage 2: exclusive scan of block sums (1 block) --------------
__global__ __launch_bounds__(512) void gcn_scan2() {
    __shared__ int sh[512];
    int t = threadIdx.x;
    int v = (t < SCAN_BLOCKS) ? g_bsum[t] : 0;
    sh[t] = v;
    __syncthreads();
    for (int off = 1; off < 512; off <<= 1) {   // Hillis-Steele inclusive
        int add = (t >= off) ? sh[t - off] : 0;
        __syncthreads();
        sh[t] += add;
        __syncthreads();
    }
    if (t < SCAN_BLOCKS) g_bsum_ex[t] = sh[t] - v;
    if (t == 511) g_rowptr[N_NODES] = sh[511];  // total edge count
}

// ---------------- scan stage 3: local scan + add-back; fused deg_inv ----------------
__global__ __launch_bounds__(256) void gcn_scan3() {
    __shared__ int sh[256];
    int i = blockIdx.x * 256 + threadIdx.x;
    int c = (i < N_NODES) ? g_cnt[i] : 0;
    int t = threadIdx.x;
    sh[t] = c;
    __syncthreads();
    for (int off = 1; off < 256; off <<= 1) {
        int add = (t >= off) ? sh[t - off] : 0;
        __syncthreads();
        sh[t] += add;
        __syncthreads();
    }
    if (i < N_NODES) {
        int start = g_bsum_ex[blockIdx.x] + sh[t] - c;  // exclusive prefix
        g_rowptr[i] = start;
        g_woff[i]   = start;
        g_deginv[i] = 1.0f / fmaxf(g_deginv[i], 1.0f);  // fused
    }
}

// ---------------- fill: csr[pos] = src, grouped by dst -------------------------------
__global__ void gcn_fill() {
    int e = blockIdx.x * blockDim.x + threadIdx.x;
    if (e >= N_EDGES) return;
    int2 sd = g_edge[e];
    int pos = atomicAdd(&g_woff[sd.y], 1);
    g_csr[pos] = sd.x;
}

// ---------------- fused prologue + GEMM ----------------------------------------------
// g_t[n,:] = prologue(in[n,:]) @ W ; prologue(x) = (relu(x+bias))? * deg_inv[n]
__global__ __launch_bounds__(256) void gcn_gemm(
    const float* __restrict__ in_ext, const float* __restrict__ W,
    const float* __restrict__ bias, int use_relu)
{
    __shared__ float Ws[D][D];
    __shared__ float Xs[64][D + 1];

    const float* in = in_ext ? in_ext : g_agg;

    const int tid = threadIdx.x;
    const int n0  = blockIdx.x * 64;

    {
        const float4* w4 = (const float4*)W;
        float4* ws4 = (float4*)&Ws[0][0];
        #pragma unroll
        for (int i = tid; i < (D * D) / 4; i += 256) ws4[i] = w4[i];
    }
    #pragma unroll 4
    for (int i = tid; i < 64 * D; i += 256) {
        int r = i >> 6, k = i & 63;
        int row = n0 + r;
        float x = 0.0f;
        if (row < N_NODES) {
            x = in[(size_t)row * D + k];
            if (use_relu) x = fmaxf(x + bias[k], 0.0f);
            x *= g_deginv[row];
        }
        Xs[r][k] = x;
    }
    __syncthreads();

    const int r  = tid >> 2;
    const int c0 = (tid & 3) * 16;
    float acc[16];
    #pragma unroll
    for (int i = 0; i < 16; i++) acc[i] = 0.0f;

    #pragma unroll
    for (int k = 0; k < D; k++) {
        float x = Xs[r][k];
        #pragma unroll
        for (int q = 0; q < 4; q++) {
            float4 w = *(const float4*)&Ws[k][c0 + q * 4];
            acc[q*4+0] += x * w.x; acc[q*4+1] += x * w.y;
            acc[q*4+2] += x * w.z; acc[q*4+3] += x * w.w;
        }
    }

    int row = n0 + r;
    if (row < N_NODES) {
        float* o = g_t + (size_t)row * D + c0;
        #pragma unroll
        for (int q = 0; q < 4; q++)
            *(float4*)(o + q * 4) = make_float4(acc[q*4+0], acc[q*4+1],
                                                acc[q*4+2], acc[q*4+3]);
    }
}

// ---------------- aggregate (NO atomics): g_agg[n] = sum_{e in CSR[n]} g_t[src(e)] --
// 16 lanes per node (lane owns one float4 of the row), 16 nodes per 256-thread block.
__global__ __launch_bounds__(256) void gcn_aggregate()
{
    int node = blockIdx.x * 16 + (threadIdx.x >> 4);
    int lane = threadIdx.x & 15;
    if (node >= N_NODES) return;

    int beg = g_rowptr[node];
    int end = g_rowptr[node + 1];

    float4 acc = make_float4(0.f, 0.f, 0.f, 0.f);
    int e = beg;

    // 4-edge batches: front-load indices + gathers for MLP
    for (; e + 4 <= end; e += 4) {
        int s0 = g_csr[e], s1 = g_csr[e+1], s2 = g_csr[e+2], s3 = g_csr[e+3];
        float4 v0 = __ldg((const float4*)(g_t + (size_t)s0 * D) + lane);
        float4 v1 = __ldg((const float4*)(g_t + (size_t)s1 * D) + lane);
        float4 v2 = __ldg((const float4*)(g_t + (size_t)s2 * D) + lane);
        float4 v3 = __ldg((const float4*)(g_t + (size_t)s3 * D) + lane);
        acc.x += v0.x + v1.x + v2.x + v3.x;
        acc.y += v0.y + v1.y + v2.y + v3.y;
        acc.z += v0.z + v1.z + v2.z + v3.z;
        acc.w += v0.w + v1.w + v2.w + v3.w;
    }
    for (; e < end; e++) {
        int s = g_csr[e];
        float4 v = __ldg((const float4*)(g_t + (size_t)s * D) + lane);
        acc.x += v.x; acc.y += v.y; acc.z += v.z; acc.w += v.w;
    }

    *((float4*)(g_agg + (size_t)node * D) + lane) = acc;
}

// ---------------- finalize: out = agg + b2; column means -----------------------------
__global__ __launch_bounds__(256) void gcn_finalize(
    const float* __restrict__ b2, float* __restrict__ out)
{
    const int j  = threadIdx.x & 63;
    const float bj = b2[j];
    float sum = 0.0f;

    const size_t total  = (size_t)N_NODES * D;
    const size_t stride = (size_t)gridDim.x * blockDim.x;
    for (size_t idx = (size_t)blockIdx.x * blockDim.x + threadIdx.x;
         idx < total; idx += stride) {
        float v = g_agg[idx] + bj;
        out[idx] = v;
        sum += v;
    }

    __shared__ float sdata[256];
    sdata[threadIdx.x] = sum;
    __syncthreads();
    if (threadIdx.x < 64) {
        float tot = sdata[threadIdx.x] + sdata[threadIdx.x + 64]
                  + sdata[threadIdx.x + 128] + sdata[threadIdx.x + 192];
        atomicAdd(&g_msum[threadIdx.x], (double)tot);
    }
}

__global__ void gcn_mean_write(float* __restrict__ out) {
    int j = threadIdx.x;
    if (j < D) out[(size_t)N_NODES * D + j] = (float)(g_msum[j] / (double)N_NODES);
}

// ---------------- launch ---------------------------------------------------------------
extern "C" void kernel_launch(void* const* d_in, const int* in_sizes, int n_in,
                              void* d_out, int out_size)
{
    const float* features = (const float*)d_in[0];
    const void*  src      = d_in[1];
    const void*  dst      = d_in[2];
    const float* W0 = (const float*)d_in[3];
    const float* b0 = (const float*)d_in[4];
    const float* W1 = (const float*)d_in[5];
    const float* b1 = (const float*)d_in[6];
    const float* W2 = (const float*)d_in[7];
    const float* b2 = (const float*)d_in[8];
    float* out = (float*)d_out;

    const int threads      = 256;
    const int blocks_edges = (N_EDGES + threads - 1) / threads;   // 6250
    const int blocks_nodes = SCAN_BLOCKS;                         // 391
    const int blocks_gemm  = (N_NODES + 63) / 64;                 // 1563
    const int blocks_agg   = (N_NODES + 15) / 16;                 // 6250

    // CSR build + degrees (all capture-safe kernels)
    gcn_detect_idx<<<1, 1>>>(src);
    gcn_init<<<blocks_nodes, threads>>>();
    gcn_prep<<<blocks_edges, threads>>>(src, dst);
    gcn_scan1<<<SCAN_BLOCKS, 256>>>();
    gcn_scan2<<<1, 512>>>();
    gcn_scan3<<<SCAN_BLOCKS, 256>>>();
    gcn_fill<<<blocks_edges, threads>>>();

    // layer 0
    gcn_gemm<<<blocks_gemm, threads>>>(features, W0, nullptr, 0);
    gcn_aggregate<<<blocks_agg, threads>>>();
    // layer 1
    gcn_gemm<<<blocks_gemm, threads>>>(nullptr, W1, b0, 1);
    gcn_aggregate<<<blocks_agg, threads>>>();
    // layer 2
    gcn_gemm<<<blocks_gemm, threads>>>(nullptr, W2, b1, 1);
    gcn_aggregate<<<blocks_agg, threads>>>();

    gcn_finalize<<<512, threads>>>(b2, out);
    gcn_mean_write<<<1, 64>>>(out);
}

// round 6
// speedup vs baseline: 1.5425x; 1.0962x over previous
#include <cuda_runtime.h>
#include <cuda_bf16.h>
#include <cstdint>

#define N_NODES 100000
#define N_EDGES 1600000
#define D 64
#define SCAN_BLOCKS 391   // ceil(N_NODES/256)

// ---------------- scratch (static device globals; no allocation) ----------------
__device__ __align__(16) float  g_t[(size_t)N_NODES * D];   // transformed features
__device__ __align__(16) float  g_agg[(size_t)N_NODES * D]; // aggregation output
__device__ __align__(16) int    g_csr[N_EDGES];             // src ids grouped by dst
__device__ __align__(16) int    g_rowptr[N_NODES + 1];
__device__ __align__(16) int    g_woff[N_NODES];            // fill cursors
__device__ __align__(16) int    g_cnt[N_NODES];             // in-degree (dst) histogram
__device__ __align__(16) float  g_deginv[N_NODES];          // 1/max(out_degree,1)
__device__ __align__(16) int    g_bsum[SCAN_BLOCKS];        // scan partials
__device__ __align__(16) int    g_bsum_ex[SCAN_BLOCKS];
__device__ __align__(16) float  g_msum[D];                  // column-sum accumulator
__device__ int g_is64;

// ---------------- helpers ----------------------------------------------------------
__device__ __forceinline__ int idx_at(const void* __restrict__ p, int e, int is64) {
    return is64 ? (int)((const long long*)p)[e] : ((const int*)p)[e];
}

// ---------------- init: zero histograms + msum; fused index-dtype detection --------
__global__ void gcn_init(const void* __restrict__ src) {
    int i = blockIdx.x * blockDim.x + threadIdx.x;
    if (i < N_NODES) { g_cnt[i] = 0; g_deginv[i] = 0.0f; }
    if (i < D)       g_msum[i] = 0.0f;
    if (i == 0) {    // detect: JAX int64 silently -> int32 unless x64 enabled
        const long long* p = (const long long*)src;
        int ok = 1;
        for (int k = 0; k < 256; k++) {
            long long v = p[k];
            if (v < 0 || v >= N_NODES) { ok = 0; break; }
        }
        g_is64 = ok;
    }
}

// ---------------- prepass: both histograms ------------------------------------------
__global__ void gcn_prep(const void* __restrict__ src, const void* __restrict__ dst) {
    int e = blockIdx.x * blockDim.x + threadIdx.x;
    if (e >= N_EDGES) return;
    const int is64 = g_is64;
    int s = idx_at(src, e, is64);
    int d = idx_at(dst, e, is64);
    if ((unsigned)s >= N_NODES) s = 0;
    if ((unsigned)d >= N_NODES) d = 0;
    atomicAdd(&g_deginv[s], 1.0f);   // out-degree (float, inverted in scan3)
    atomicAdd(&g_cnt[d], 1);         // in-degree for CSR
}

// ---------------- scan stage 1: per-block sums ----------------------------------------
__global__ __launch_bounds__(256) void gcn_scan1() {
    __shared__ int sh[256];
    int i = blockIdx.x * 256 + threadIdx.x;
    sh[threadIdx.x] = (i < N_NODES) ? g_cnt[i] : 0;
    __syncthreads();
    for (int off = 128; off > 0; off >>= 1) {
        if (threadIdx.x < off) sh[threadIdx.x] += sh[threadIdx.x + off];
        __syncthreads();
    }
    if (threadIdx.x == 0) g_bsum[blockIdx.x] = sh[0];
}

// ---------------- scan stage 2: exclusive scan of block sums (1 block) ----------------
__global__ __launch_bounds__(512) void gcn_scan2() {
    __shared__ int sh[512];
    int t = threadIdx.x;
    int v = (t < SCAN_BLOCKS) ? g_bsum[t] : 0;
    sh[t] = v;
    __syncthreads();
    for (int off = 1; off < 512; off <<= 1) {
        int add = (t >= off) ? sh[t - off] : 0;
        __syncthreads();
        sh[t] += add;
        __syncthreads();
    }
    if (t < SCAN_BLOCKS) g_bsum_ex[t] = sh[t] - v;
    if (t == 511) g_rowptr[N_NODES] = sh[511];
}

// ---------------- scan stage 3: local scan + add-back; fused deg_inv ------------------
__global__ __launch_bounds__(256) void gcn_scan3() {
    __shared__ int sh[256];
    int i = blockIdx.x * 256 + threadIdx.x;
    int t = threadIdx.x;
    int c = (i < N_NODES) ? g_cnt[i] : 0;
    sh[t] = c;
    __syncthreads();
    for (int off = 1; off < 256; off <<= 1) {
        int add = (t >= off) ? sh[t - off] : 0;
        __syncthreads();
        sh[t] += add;
        __syncthreads();
    }
    if (i < N_NODES) {
        int start = g_bsum_ex[blockIdx.x] + sh[t] - c;
        g_rowptr[i] = start;
        g_woff[i]   = start;
        g_deginv[i] = 1.0f / fmaxf(g_deginv[i], 1.0f);
    }
}

// ---------------- fill: csr[pos] = src, grouped by dst (re-decodes indices) -----------
__global__ void gcn_fill(const void* __restrict__ src, const void* __restrict__ dst) {
    int e = blockIdx.x * blockDim.x + threadIdx.x;
    if (e >= N_EDGES) return;
    const int is64 = g_is64;
    int s = idx_at(src, e, is64);
    int d = idx_at(dst, e, is64);
    if ((unsigned)s >= N_NODES) s = 0;
    if ((unsigned)d >= N_NODES) d = 0;
    int pos = atomicAdd(&g_woff[d], 1);
    g_csr[pos] = s;
}

// ---------------- fused prologue + GEMM, 2 rows x 16 cols per thread -------------------
// g_t[n,:] = prologue(in[n,:]) @ W ; prologue(x) = (relu(x+bias))? * deg_inv[n]
// 128 threads, 64 rows per block. Halves W smem traffic vs 1-row scheme.
__global__ __launch_bounds__(128) void gcn_gemm(
    const float* __restrict__ in_ext, const float* __restrict__ W,
    const float* __restrict__ bias, int use_relu)
{
    __shared__ float Ws[D][D];        // 16 KB
    __shared__ float Xs[64][68];      // rows 272B -> float4-aligned; bank=(4r+k)%32

    const float* in = in_ext ? in_ext : g_agg;
    const int tid = threadIdx.x;
    const int n0  = blockIdx.x * 64;

    // W -> smem (1024 float4 / 128 thr = 8 each)
    {
        const float4* w4 = (const float4*)W;
        float4* ws4 = (float4*)&Ws[0][0];
        #pragma unroll
        for (int i = tid; i < (D * D) / 4; i += 128) ws4[i] = w4[i];
    }
    // X rows -> smem with fused prologue (float4 granularity)
    for (int i = tid; i < 64 * (D / 4); i += 128) {
        int r = i >> 4, q = i & 15;           // q = float4 index in row
        int row = n0 + r;
        float4 x = make_float4(0.f, 0.f, 0.f, 0.f);
        if (row < N_NODES) {
            x = __ldg((const float4*)(in + (size_t)row * D) + q);
            if (use_relu) {
                float4 b = __ldg((const float4*)bias + q);
                x.x = fmaxf(x.x + b.x, 0.f); x.y = fmaxf(x.y + b.y, 0.f);
                x.z = fmaxf(x.z + b.z, 0.f); x.w = fmaxf(x.w + b.w, 0.f);
            }
            float di = g_deginv[row];
            x.x *= di; x.y *= di; x.z *= di; x.w *= di;
        }
        *(float4*)&Xs[r][q * 4] = x;
    }
    __syncthreads();

    const int rb = tid >> 2;          // rows rb and rb+32
    const int c0 = (tid & 3) * 16;    // 16 output cols
    float acc0[16], acc1[16];
    #pragma unroll
    for (int i = 0; i < 16; i++) { acc0[i] = 0.f; acc1[i] = 0.f; }

    #pragma unroll
    for (int k = 0; k < D; k++) {
        float x0 = Xs[rb][k];
        float x1 = Xs[rb + 32][k];
        #pragma unroll
        for (int q = 0; q < 4; q++) {
            float4 w = *(const float4*)&Ws[k][c0 + q * 4];
            acc0[q*4+0] += x0 * w.x; acc0[q*4+1] += x0 * w.y;
            acc0[q*4+2] += x0 * w.z; acc0[q*4+3] += x0 * w.w;
            acc1[q*4+0] += x1 * w.x; acc1[q*4+1] += x1 * w.y;
            acc1[q*4+2] += x1 * w.z; acc1[q*4+3] += x1 * w.w;
        }
    }

    int row0 = n0 + rb, row1 = n0 + rb + 32;
    if (row0 < N_NODES) {
        float* o = g_t + (size_t)row0 * D + c0;
        #pragma unroll
        for (int q = 0; q < 4; q++)
            *(float4*)(o + q*4) = make_float4(acc0[q*4+0], acc0[q*4+1],
                                              acc0[q*4+2], acc0[q*4+3]);
    }
    if (row1 < N_NODES) {
        float* o = g_t + (size_t)row1 * D + c0;
        #pragma unroll
        for (int q = 0; q < 4; q++)
            *(float4*)(o + q*4) = make_float4(acc1[q*4+0], acc1[q*4+1],
                                              acc1[q*4+2], acc1[q*4+3]);
    }
}

// ---------------- aggregate core: acc = sum_{e in CSR[node]} g_t[src(e)][lane] --------
__device__ __forceinline__ float4 agg_node(int node, int lane) {
    int beg = __ldg(&g_rowptr[node]);
    int end = __ldg(&g_rowptr[node + 1]);
    float4 acc = make_float4(0.f, 0.f, 0.f, 0.f);
    int e = beg;
    for (; e + 4 <= end; e += 4) {
        int s0 = __ldg(&g_csr[e]),   s1 = __ldg(&g_csr[e+1]);
        int s2 = __ldg(&g_csr[e+2]), s3 = __ldg(&g_csr[e+3]);
        float4 v0 = __ldg((const float4*)(g_t + (size_t)s0 * D) + lane);
        float4 v1 = __ldg((const float4*)(g_t + (size_t)s1 * D) + lane);
        float4 v2 = __ldg((const float4*)(g_t + (size_t)s2 * D) + lane);
        float4 v3 = __ldg((const float4*)(g_t + (size_t)s3 * D) + lane);
        acc.x += v0.x + v1.x + v2.x + v3.x;
        acc.y += v0.y + v1.y + v2.y + v3.y;
        acc.z += v0.z + v1.z + v2.z + v3.z;
        acc.w += v0.w + v1.w + v2.w + v3.w;
    }
    for (; e < end; e++) {
        int s = __ldg(&g_csr[e]);
        float4 v = __ldg((const float4*)(g_t + (size_t)s * D) + lane);
        acc.x += v.x; acc.y += v.y; acc.z += v.z; acc.w += v.w;
    }
    return acc;
}

// ---------------- aggregate (layers 0,1): writes g_agg ---------------------------------
__global__ __launch_bounds__(256) void gcn_aggregate()
{
    int node = blockIdx.x * 16 + (threadIdx.x >> 4);
    int lane = threadIdx.x & 15;
    if (node >= N_NODES) return;
    float4 acc = agg_node(node, lane);
    *((float4*)(g_agg + (size_t)node * D) + lane) = acc;
}

// ---------------- aggregate final (layer 2): +b2, write out, fused column sums --------
// N_NODES % 16 == 0 -> every thread has a valid node (no guard needed).
__global__ __launch_bounds__(256) void gcn_aggregate_final(
    const float* __restrict__ b2, float* __restrict__ out)
{
    int node = blockIdx.x * 16 + (threadIdx.x >> 4);
    int lane = threadIdx.x & 15;

    float4 acc = agg_node(node, lane);
    float4 bb  = __ldg((const float4*)b2 + lane);
    acc.x += bb.x; acc.y += bb.y; acc.z += bb.z; acc.w += bb.w;
    *((float4*)(out + (size_t)node * D) + lane) = acc;

    // block-level column-sum reduction (16 groups x 16 lanes)
    __shared__ float4 sdata[256];
    sdata[threadIdx.x] = acc;
    __syncthreads();
    #pragma unroll
    for (int off = 128; off >= 16; off >>= 1) {
        if (threadIdx.x < off) {
            float4 o = sdata[threadIdx.x + off];
            sdata[threadIdx.x].x += o.x; sdata[threadIdx.x].y += o.y;
            sdata[threadIdx.x].z += o.z; sdata[threadIdx.x].w += o.w;
        }
        __syncthreads();
    }
    if (threadIdx.x < 16) {
        float4 s = sdata[threadIdx.x];
        atomicAdd(&g_msum[threadIdx.x * 4 + 0], s.x);
        atomicAdd(&g_msum[threadIdx.x * 4 + 1], s.y);
        atomicAdd(&g_msum[threadIdx.x * 4 + 2], s.z);
        atomicAdd(&g_msum[threadIdx.x * 4 + 3], s.w);
    }
}

__global__ void gcn_mean_write(float* __restrict__ out) {
    int j = threadIdx.x;
    if (j < D) out[(size_t)N_NODES * D + j] = g_msum[j] / (float)N_NODES;
}

// ---------------- launch -----------------------------------------------------------------
extern "C" void kernel_launch(void* const* d_in, const int* in_sizes, int n_in,
                              void* d_out, int out_size)
{
    const float* features = (const float*)d_in[0];
    const void*  src      = d_in[1];
    const void*  dst      = d_in[2];
    const float* W0 = (const float*)d_in[3];
    const float* b0 = (const float*)d_in[4];
    const float* W1 = (const float*)d_in[5];
    const float* b1 = (const float*)d_in[6];
    const float* W2 = (const float*)d_in[7];
    const float* b2 = (const float*)d_in[8];
    float* out = (float*)d_out;

    const int threads      = 256;
    const int blocks_edges = (N_EDGES + threads - 1) / threads;   // 6250
    const int blocks_gemm  = (N_NODES + 63) / 64;                 // 1563
    const int blocks_agg   = N_NODES / 16;                        // 6250 (exact)

    // CSR build + degrees
    gcn_init<<<SCAN_BLOCKS, threads>>>(src);
    gcn_prep<<<blocks_edges, threads>>>(src, dst);
    gcn_scan1<<<SCAN_BLOCKS, 256>>>();
    gcn_scan2<<<1, 512>>>();
    gcn_scan3<<<SCAN_BLOCKS, 256>>>();
    gcn_fill<<<blocks_edges, threads>>>(src, dst);

    // layer 0
    gcn_gemm<<<blocks_gemm, 128>>>(features, W0, nullptr, 0);
    gcn_aggregate<<<blocks_agg, threads>>>();
    // layer 1
    gcn_gemm<<<blocks_gemm, 128>>>(nullptr, W1, b0, 1);
    gcn_aggregate<<<blocks_agg, threads>>>();
    // layer 2 (epilogue fused into aggregate)
    gcn_gemm<<<blocks_gemm, 128>>>(nullptr, W2, b1, 1);
    gcn_aggregate_final<<<blocks_agg, threads>>>(b2, out);

    gcn_mean_write<<<1, 64>>>(out);
}